// round 5
// baseline (speedup 1.0000x reference)
#include <cuda_runtime.h>
#include <math.h>

#define N_BINS 1024
#define N_COPIES 8          // per-warp-pair privatized histogram (16 warps / 8 copies)
#define HIST_BLOCKS 592     // 4 * 148 SMs
#define HIST_THREADS 512
#define CHUNK_INTS 2048     // 8 KB per chunk; 2^24 / 2^11 = 8192 chunks exactly
#define CHUNK_BYTES (CHUNK_INTS * 4)

__device__ unsigned int g_counts[N_BINS];     // zero at load; reset each run below
__device__ unsigned int g_done;               // arrival counter, reset each run

__device__ __forceinline__ unsigned int smem_u32(const void* p) {
    return (unsigned int)__cvta_generic_to_shared(p);
}
__device__ __forceinline__ void mbar_init(unsigned int mbar, unsigned int count) {
    asm volatile("mbarrier.init.shared.b64 [%0], %1;" :: "r"(mbar), "r"(count) : "memory");
}
__device__ __forceinline__ void mbar_expect_tx(unsigned int mbar, unsigned int bytes) {
    asm volatile("mbarrier.arrive.expect_tx.shared.b64 _, [%0], %1;"
                 :: "r"(mbar), "r"(bytes) : "memory");
}
__device__ __forceinline__ void tma_bulk_g2s(unsigned int dst, const void* src,
                                             unsigned int bytes, unsigned int mbar) {
    asm volatile(
        "cp.async.bulk.shared::cluster.global.mbarrier::complete_tx::bytes [%0], [%1], %2, [%3];"
        :: "r"(dst), "l"(src), "r"(bytes), "r"(mbar) : "memory");
}
__device__ __forceinline__ void mbar_wait(unsigned int mbar, unsigned int parity) {
    while (true) {
        unsigned int done;
        asm volatile(
            "{\n\t.reg .pred p;\n\t"
            "mbarrier.try_wait.parity.shared.b64 p, [%1], %2;\n\t"
            "selp.b32 %0, 1, 0, p;\n\t}"
            : "=r"(done) : "r"(mbar), "r"(parity) : "memory");
        if (done) break;
    }
}
__device__ __forceinline__ void fence_proxy_async_cta() {
    asm volatile("fence.proxy.async.shared::cta;" ::: "memory");
}

__global__ void __launch_bounds__(HIST_THREADS, 4) hist_kernel(
    const int* __restrict__ idx, long long n, float inv_n,
    float* __restrict__ out)
{
    __shared__ __align__(16) int buf[2][CHUNK_INTS];          // 16 KB staging
    __shared__ unsigned int sh[N_COPIES][N_BINS];             // 32 KB histograms
    __shared__ __align__(8) unsigned long long mbar_s[2];
    __shared__ bool s_last;
    __shared__ float red[HIST_THREADS / 32];

    const int tid = threadIdx.x;
    const unsigned int mb0 = smem_u32(&mbar_s[0]);
    const unsigned int mb1 = smem_u32(&mbar_s[1]);
    const unsigned int bufsa[2] = { smem_u32(&buf[0][0]), smem_u32(&buf[1][0]) };

    // zero privatized histograms
    unsigned int* flat = &sh[0][0];
    for (int i = tid; i < N_COPIES * N_BINS; i += blockDim.x) flat[i] = 0u;

    if (tid == 0) {
        mbar_init(mb0, 1);
        mbar_init(mb1, 1);
        fence_proxy_async_cta();
    }
    __syncthreads();

    // 16 warps share 8 copies
    unsigned int* h = sh[(tid >> 5) & (N_COPIES - 1)];

    const long long n_chunks = n / CHUNK_INTS;
    const long long cstride  = (long long)gridDim.x;

    // prologue: issue up to 2 chunks
    if (tid == 0) {
        long long c = blockIdx.x;
        if (c < n_chunks) { mbar_expect_tx(mb0, CHUNK_BYTES);
                            tma_bulk_g2s(bufsa[0], idx + c * CHUNK_INTS, CHUNK_BYTES, mb0); }
        c += cstride;
        if (c < n_chunks) { mbar_expect_tx(mb1, CHUNK_BYTES);
                            tma_bulk_g2s(bufsa[1], idx + c * CHUNK_INTS, CHUNK_BYTES, mb1); }
    }

    int slot = 0;
    unsigned int phase[2] = {0u, 0u};
    const unsigned int mbs[2] = { mb0, mb1 };

    for (long long c = blockIdx.x; c < n_chunks; c += cstride) {
        mbar_wait(mbs[slot], phase[slot]);
        phase[slot] ^= 1u;

        // 2048 ints / 512 threads = one int4 per thread, conflict-free LDS.128
        int4 v = ((const int4*)buf[slot])[tid];
        atomicAdd(&h[v.x & (N_BINS - 1)], 1u);
        atomicAdd(&h[v.y & (N_BINS - 1)], 1u);
        atomicAdd(&h[v.z & (N_BINS - 1)], 1u);
        atomicAdd(&h[v.w & (N_BINS - 1)], 1u);

        __syncthreads();   // all reads of buf[slot] done before refill

        if (tid == 0) {
            long long nc = c + 2 * cstride;
            if (nc < n_chunks) {
                fence_proxy_async_cta();
                mbar_expect_tx(mbs[slot], CHUNK_BYTES);
                tma_bulk_g2s(bufsa[slot], idx + nc * CHUNK_INTS, CHUNK_BYTES, mbs[slot]);
            }
        }
        slot ^= 1;
    }

    // tail (n not a multiple of CHUNK_INTS) — plain LDG, tiny or empty
    for (long long r = n_chunks * CHUNK_INTS + blockIdx.x * (long long)blockDim.x + tid;
         r < n; r += (long long)gridDim.x * blockDim.x)
        atomicAdd(&h[idx[r] & (N_BINS - 1)], 1u);

    __syncthreads();

    // flush per-copy sums -> global histogram (1 REDG per bin per block)
    for (int b = tid; b < N_BINS; b += blockDim.x) {
        unsigned int s = 0;
        #pragma unroll
        for (int cc = 0; cc < N_COPIES; cc++) s += sh[cc][b];
        atomicAdd(&g_counts[b], s);
    }

    // last-block-done: fused finalize
    __threadfence();
    if (tid == 0)
        s_last = (atomicAdd(&g_done, 1u) == (unsigned)(gridDim.x - 1));
    __syncthreads();

    if (s_last) {
        volatile unsigned int* gc = g_counts;
        float v = 0.0f;
        #pragma unroll
        for (int k = 0; k < N_BINS / HIST_THREADS; k++) {
            int b = tid + k * HIST_THREADS;
            unsigned int c = gc[b];
            g_counts[b] = 0u;                 // reset for next replay
            float p = (float)c * inv_n;
            v += p * logf(p + 1e-8f);
        }
        #pragma unroll
        for (int o = 16; o > 0; o >>= 1) v += __shfl_down_sync(0xFFFFFFFFu, v, o);
        if ((tid & 31) == 0) red[tid >> 5] = v;
        __syncthreads();
        if (tid < 32) {
            float s = (tid < HIST_THREADS / 32) ? red[tid] : 0.0f;
            #pragma unroll
            for (int o = 8; o > 0; o >>= 1) s += __shfl_down_sync(0xFFFFFFFFu, s, o);
            if (tid == 0) {
                out[0] = expf(-s);
                g_done = 0u;                  // reset arrival counter for next replay
            }
        }
    }
}

extern "C" void kernel_launch(void* const* d_in, const int* in_sizes, int n_in,
                              void* d_out, int out_size) {
    const int* idx = (const int*)d_in[0];
    long long n    = (long long)in_sizes[0];
    float* out     = (float*)d_out;

    hist_kernel<<<HIST_BLOCKS, HIST_THREADS>>>(idx, n, 1.0f / (float)n, out);
}

// round 6
// speedup vs baseline: 1.0964x; 1.0964x over previous
#include <cuda_runtime.h>
#include <math.h>

#define N_BINS 1024
#define N_COPIES 8           // one PRIVATE smem histogram per warp (256 thr / 32)
#define BLOCKS_PER_SM 7      // 7 * 32KB = 224KB smem <= 228KB
#define HIST_BLOCKS (148 * BLOCKS_PER_SM)   // 1036
#define HIST_THREADS 256

__device__ unsigned int g_counts[N_BINS];     // zero at load; reset each run below
__device__ unsigned int g_done;               // arrival counter, reset each run

__global__ void __launch_bounds__(HIST_THREADS, BLOCKS_PER_SM) hist_kernel(
    const int* __restrict__ idx, long long n, float inv_n,
    float* __restrict__ out)
{
    __shared__ unsigned int sh[N_COPIES][N_BINS];
    __shared__ bool s_last;
    __shared__ float red[HIST_THREADS / 32];

    unsigned int* flat = &sh[0][0];
    for (int i = threadIdx.x; i < N_COPIES * N_BINS; i += blockDim.x)
        flat[i] = 0u;
    __syncthreads();

    unsigned int* h = sh[threadIdx.x >> 5];   // fully private per-warp copy

    long long tid    = (long long)blockIdx.x * blockDim.x + threadIdx.x;
    long long stride = (long long)gridDim.x * blockDim.x;
    long long n4     = n >> 2;
    const int4* p4   = (const int4*)idx;

    // main loop: 2 outstanding int4 loads per iteration for MLP
    long long i = tid;
    for (; i + stride < n4; i += 2 * stride) {
        int4 a = p4[i];
        int4 b = p4[i + stride];
        atomicAdd(&h[a.x & (N_BINS - 1)], 1u);
        atomicAdd(&h[a.y & (N_BINS - 1)], 1u);
        atomicAdd(&h[a.z & (N_BINS - 1)], 1u);
        atomicAdd(&h[a.w & (N_BINS - 1)], 1u);
        atomicAdd(&h[b.x & (N_BINS - 1)], 1u);
        atomicAdd(&h[b.y & (N_BINS - 1)], 1u);
        atomicAdd(&h[b.z & (N_BINS - 1)], 1u);
        atomicAdd(&h[b.w & (N_BINS - 1)], 1u);
    }
    for (; i < n4; i += stride) {
        int4 a = p4[i];
        atomicAdd(&h[a.x & (N_BINS - 1)], 1u);
        atomicAdd(&h[a.y & (N_BINS - 1)], 1u);
        atomicAdd(&h[a.z & (N_BINS - 1)], 1u);
        atomicAdd(&h[a.w & (N_BINS - 1)], 1u);
    }
    // remainder (n not multiple of 4)
    for (long long r = (n4 << 2) + tid; r < n; r += stride)
        atomicAdd(&h[idx[r] & (N_BINS - 1)], 1u);

    __syncthreads();

    // flush per-warp copies -> global histogram (1 REDG per bin per block)
    for (int b = threadIdx.x; b < N_BINS; b += blockDim.x) {
        unsigned int s = 0;
        #pragma unroll
        for (int c = 0; c < N_COPIES; c++) s += sh[c][b];
        atomicAdd(&g_counts[b], s);
    }

    // last-block-done: fused finalize
    __threadfence();
    if (threadIdx.x == 0)
        s_last = (atomicAdd(&g_done, 1u) == (unsigned)(gridDim.x - 1));
    __syncthreads();

    if (s_last) {
        int t = threadIdx.x;
        volatile unsigned int* gc = g_counts;
        float v = 0.0f;
        #pragma unroll
        for (int k = 0; k < N_BINS / HIST_THREADS; k++) {
            int b = t + k * HIST_THREADS;
            unsigned int c = gc[b];
            g_counts[b] = 0u;                 // reset for next replay
            float p = (float)c * inv_n;
            v += p * logf(p + 1e-8f);
        }
        #pragma unroll
        for (int o = 16; o > 0; o >>= 1) v += __shfl_down_sync(0xFFFFFFFFu, v, o);
        if ((t & 31) == 0) red[t >> 5] = v;
        __syncthreads();
        if (t < 32) {
            float s = (t < HIST_THREADS / 32) ? red[t] : 0.0f;
            #pragma unroll
            for (int o = 4; o > 0; o >>= 1) s += __shfl_down_sync(0xFFFFFFFFu, s, o);
            if (t == 0) {
                out[0] = expf(-s);
                g_done = 0u;                  // reset arrival counter for next replay
            }
        }
    }
}

extern "C" void kernel_launch(void* const* d_in, const int* in_sizes, int n_in,
                              void* d_out, int out_size) {
    const int* idx = (const int*)d_in[0];
    long long n    = (long long)in_sizes[0];
    float* out     = (float*)d_out;

    hist_kernel<<<HIST_BLOCKS, HIST_THREADS>>>(idx, n, 1.0f / (float)n, out);
}

// round 7
// speedup vs baseline: 1.2297x; 1.1216x over previous
#include <cuda_runtime.h>
#include <math.h>

#define N_BINS 1024
#define N_GROUPS 4            // lane-group copies: g = lane & 3; bank class g (mod 4)
#define HIST_BLOCKS 592       // 4 * 148 SMs (best-known from R3)
#define HIST_THREADS 256

__device__ unsigned int g_counts[N_BINS];     // zero at load; reset each run below
__device__ unsigned int g_done;               // arrival counter, reset each run

__global__ void __launch_bounds__(HIST_THREADS) hist_kernel(
    const int* __restrict__ idx, long long n, float inv_n,
    float* __restrict__ out)
{
    // sh[bin*4 + g]: bank = (bin*4+g)&31 ≡ g (mod 4) -> the 4 lane-groups
    // never bank-conflict with each other; conflicts only within 8-lane groups.
    __shared__ __align__(16) unsigned int sh[N_BINS * N_GROUPS];   // 16 KB
    __shared__ bool s_last;
    __shared__ float red[HIST_THREADS / 32];

    for (int i = threadIdx.x; i < N_BINS * N_GROUPS; i += blockDim.x)
        sh[i] = 0u;
    __syncthreads();

    const unsigned int g = threadIdx.x & (N_GROUPS - 1);

    long long tid    = (long long)blockIdx.x * blockDim.x + threadIdx.x;
    long long stride = (long long)gridDim.x * blockDim.x;
    long long n4     = n >> 2;
    const int4* p4   = (const int4*)idx;

    #define BUMP(val) atomicAdd(&sh[(((unsigned)(val) & (N_BINS - 1)) << 2) | g], 1u)

    // main loop: 4 outstanding int4 loads per iteration for MLP
    long long i = tid;
    for (; i + 3 * stride < n4; i += 4 * stride) {
        int4 a = p4[i];
        int4 b = p4[i + stride];
        int4 c = p4[i + 2 * stride];
        int4 d = p4[i + 3 * stride];
        BUMP(a.x); BUMP(a.y); BUMP(a.z); BUMP(a.w);
        BUMP(b.x); BUMP(b.y); BUMP(b.z); BUMP(b.w);
        BUMP(c.x); BUMP(c.y); BUMP(c.z); BUMP(c.w);
        BUMP(d.x); BUMP(d.y); BUMP(d.z); BUMP(d.w);
    }
    for (; i < n4; i += stride) {
        int4 a = p4[i];
        BUMP(a.x); BUMP(a.y); BUMP(a.z); BUMP(a.w);
    }
    // remainder (n not multiple of 4)
    for (long long r = (n4 << 2) + tid; r < n; r += stride)
        BUMP(idx[r]);
    #undef BUMP

    __syncthreads();

    // flush: one uint4 LDS per bin, one REDG per bin per block
    for (int b = threadIdx.x; b < N_BINS; b += blockDim.x) {
        uint4 q = ((const uint4*)sh)[b];
        atomicAdd(&g_counts[b], q.x + q.y + q.z + q.w);
    }

    // last-block-done: fused finalize
    __threadfence();
    if (threadIdx.x == 0)
        s_last = (atomicAdd(&g_done, 1u) == (unsigned)(gridDim.x - 1));
    __syncthreads();

    if (s_last) {
        int t = threadIdx.x;
        volatile unsigned int* gc = g_counts;
        float v = 0.0f;
        #pragma unroll
        for (int k = 0; k < N_BINS / HIST_THREADS; k++) {
            int b = t + k * HIST_THREADS;
            unsigned int c = gc[b];
            g_counts[b] = 0u;                 // reset for next replay
            float p = (float)c * inv_n;
            v += p * logf(p + 1e-8f);
        }
        #pragma unroll
        for (int o = 16; o > 0; o >>= 1) v += __shfl_down_sync(0xFFFFFFFFu, v, o);
        if ((t & 31) == 0) red[t >> 5] = v;
        __syncthreads();
        if (t < 32) {
            float s = (t < HIST_THREADS / 32) ? red[t] : 0.0f;
            #pragma unroll
            for (int o = 4; o > 0; o >>= 1) s += __shfl_down_sync(0xFFFFFFFFu, s, o);
            if (t == 0) {
                out[0] = expf(-s);
                g_done = 0u;                  // reset arrival counter for next replay
            }
        }
    }
}

extern "C" void kernel_launch(void* const* d_in, const int* in_sizes, int n_in,
                              void* d_out, int out_size) {
    const int* idx = (const int*)d_in[0];
    long long n    = (long long)in_sizes[0];
    float* out     = (float*)d_out;

    hist_kernel<<<HIST_BLOCKS, HIST_THREADS>>>(idx, n, 1.0f / (float)n, out);
}

// round 8
// speedup vs baseline: 1.2318x; 1.0017x over previous
#include <cuda_runtime.h>
#include <math.h>

#define N_BINS 1024
#define N_COPIES 8           // one PRIVATE smem histogram per warp (256 thr / 32)
#define HIST_BLOCKS 592      // 4 * 148 SMs (best-known R3 config)
#define HIST_THREADS 256

// bin pairs packed: g_counts64[b2] = (count[2*b2+1] << 32) | count[2*b2]
__device__ unsigned long long g_counts64[N_BINS / 2];  // zero at load; reset each run
__device__ unsigned int g_done;                        // arrival counter, reset each run

__global__ void __launch_bounds__(HIST_THREADS) hist_kernel(
    const int* __restrict__ idx, long long n, float inv_n,
    float* __restrict__ out)
{
    __shared__ __align__(16) unsigned int sh[N_COPIES][N_BINS];
    __shared__ bool s_last;
    __shared__ float red[HIST_THREADS / 32];

    unsigned int* flat = &sh[0][0];
    for (int i = threadIdx.x; i < N_COPIES * N_BINS; i += blockDim.x)
        flat[i] = 0u;
    __syncthreads();

    unsigned int* h = sh[threadIdx.x >> 5];   // fully private per-warp copy

    long long tid    = (long long)blockIdx.x * blockDim.x + threadIdx.x;
    long long stride = (long long)gridDim.x * blockDim.x;
    long long n4     = n >> 2;
    const int4* p4   = (const int4*)idx;

    #define BUMP(v) atomicAdd(&h[(unsigned)(v) & (N_BINS - 1)], 1u)

    // main loop: 4 outstanding int4 loads per iteration (MLP=4)
    long long i = tid;
    for (; i + 3 * stride < n4; i += 4 * stride) {
        int4 a = p4[i];
        int4 b = p4[i + stride];
        int4 c = p4[i + 2 * stride];
        int4 d = p4[i + 3 * stride];
        BUMP(a.x); BUMP(a.y); BUMP(a.z); BUMP(a.w);
        BUMP(b.x); BUMP(b.y); BUMP(b.z); BUMP(b.w);
        BUMP(c.x); BUMP(c.y); BUMP(c.z); BUMP(c.w);
        BUMP(d.x); BUMP(d.y); BUMP(d.z); BUMP(d.w);
    }
    for (; i < n4; i += stride) {
        int4 a = p4[i];
        BUMP(a.x); BUMP(a.y); BUMP(a.z); BUMP(a.w);
    }
    // remainder (n not multiple of 4)
    for (long long r = (n4 << 2) + tid; r < n; r += stride)
        BUMP(idx[r]);
    #undef BUMP

    __syncthreads();

    // flush: sum 8 copies per bin pair, ONE 64-bit REDG per pair per block.
    // Per-block counts <= n/HIST_BLOCKS and global sums <= n < 2^32: no carry
    // between the packed 32-bit fields.
    for (int b2 = threadIdx.x; b2 < N_BINS / 2; b2 += blockDim.x) {
        unsigned int lo = 0, hi = 0;
        #pragma unroll
        for (int c = 0; c < N_COPIES; c++) {
            uint2 q = *(const uint2*)&sh[c][2 * b2];
            lo += q.x; hi += q.y;
        }
        atomicAdd(&g_counts64[b2], ((unsigned long long)hi << 32) | lo);
    }

    // last-block-done: fused finalize
    __threadfence();
    if (threadIdx.x == 0)
        s_last = (atomicAdd(&g_done, 1u) == (unsigned)(gridDim.x - 1));
    __syncthreads();

    if (s_last) {
        int t = threadIdx.x;
        volatile unsigned long long* gc = g_counts64;
        float v = 0.0f;
        #pragma unroll
        for (int k = 0; k < (N_BINS / 2) / HIST_THREADS; k++) {
            int b2 = t + k * HIST_THREADS;
            unsigned long long c = gc[b2];
            g_counts64[b2] = 0ull;            // reset for next replay
            float p0 = (float)(unsigned int)(c & 0xFFFFFFFFull) * inv_n;
            float p1 = (float)(unsigned int)(c >> 32) * inv_n;
            v += p0 * logf(p0 + 1e-8f);
            v += p1 * logf(p1 + 1e-8f);
        }
        #pragma unroll
        for (int o = 16; o > 0; o >>= 1) v += __shfl_down_sync(0xFFFFFFFFu, v, o);
        if ((t & 31) == 0) red[t >> 5] = v;
        __syncthreads();
        if (t < 32) {
            float s = (t < HIST_THREADS / 32) ? red[t] : 0.0f;
            #pragma unroll
            for (int o = 4; o > 0; o >>= 1) s += __shfl_down_sync(0xFFFFFFFFu, s, o);
            if (t == 0) {
                out[0] = expf(-s);
                g_done = 0u;                  // reset arrival counter for next replay
            }
        }
    }
}

extern "C" void kernel_launch(void* const* d_in, const int* in_sizes, int n_in,
                              void* d_out, int out_size) {
    const int* idx = (const int*)d_in[0];
    long long n    = (long long)in_sizes[0];
    float* out     = (float*)d_out;

    hist_kernel<<<HIST_BLOCKS, HIST_THREADS>>>(idx, n, 1.0f / (float)n, out);
}